// round 7
// baseline (speedup 1.0000x reference)
#include <cuda_runtime.h>
#include <cuda_bf16.h>
#include <cstdint>

#define N_ 16384
#define T_ 60
#define M_ 8
#define LOG_2PI 1.8378770664093453f

#define BLK 256
#define UNROLL 4
#define ITEMS (N_ * T_)                 // 983040
#define IPB ((BLK / M_) * UNROLL)       // 128 items per block
#define GRID (ITEMS / IPB)              // 7680 (exact)
#define NSLOT 128

// Device-global scratch (zero-init at load; self-reset by the final block).
__device__ float g_accn[T_ * NSLOT];
__device__ float g_accd[T_ * NSLOT];
__device__ unsigned int g_ticket;

__global__ __launch_bounds__(BLK) void nll_fused_kernel(
    const float* __restrict__ mu,
    const float* __restrict__ sigma,
    const float* __restrict__ pi,
    const float* __restrict__ x,
    const float* __restrict__ mask,
    float* __restrict__ out)
{
    __shared__ float s_num[T_];
    __shared__ float s_den[T_];
    __shared__ unsigned int s_last;

    const int tid = threadIdx.x;
    const int g   = tid >> 3;           // item group within block (0..31)
    const int m   = tid & 7;            // mixture component (0..7)
    const int base = blockIdx.x * IPB;

    if (tid < T_) { s_num[tid] = 0.0f; s_den[tid] = 0.0f; }
    __syncthreads();

    const float4* sg4 = reinterpret_cast<const float4*>(sigma);
    const float2* mu2 = reinterpret_cast<const float2*>(mu);
    const float2* x2  = reinterpret_cast<const float2*>(x);

    #pragma unroll
    for (int it = 0; it < UNROLL; it++) {
        const int item = base + it * 32 + g;      // item = n*T + t
        const int n = item / T_;
        const int t = item - n * T_;

        // Fully coalesced loads: warp covers 32 consecutive (item,comp) slots.
        float4 s  = __ldg(sg4 + (size_t)item * M_ + m);   // [s00,s01,s10,s11]
        float2 mv = __ldg(mu2 + (size_t)item * M_ + m);
        float  p  = __ldg(pi + (size_t)n * M_ + m);
        float2 xv = __ldg(x2 + item);                     // 8-lane broadcast

        // Closed-form 2x2 MVN log-prob for this component
        float d0 = xv.x - mv.x, d1 = xv.y - mv.y;
        float det  = fmaf(s.x, s.w, -s.y * s.z);
        float quad = fmaf(d0 * d0, s.w, fmaf(-2.0f * s.y, d0 * d1, d1 * d1 * s.x));
        float lp   = fmaf(-0.5f, quad * __frcp_rn(det),
                          fmaf(-0.5f, __logf(det), -LOG_2PI));

        // 8-lane logsumexp over components (bfly shuffles stay in the group)
        float a  = lp + p;
        float mx = a;
        mx = fmaxf(mx, __shfl_xor_sync(0xFFFFFFFFu, mx, 1));
        mx = fmaxf(mx, __shfl_xor_sync(0xFFFFFFFFu, mx, 2));
        mx = fmaxf(mx, __shfl_xor_sync(0xFFFFFFFFu, mx, 4));
        float ea = __expf(a - mx);
        float ep = __expf(p);            // |pi| small: no max needed for pi-lse
        ea += __shfl_xor_sync(0xFFFFFFFFu, ea, 1);
        ep += __shfl_xor_sync(0xFFFFFFFFu, ep, 1);
        ea += __shfl_xor_sync(0xFFFFFFFFu, ea, 2);
        ep += __shfl_xor_sync(0xFFFFFFFFu, ep, 2);
        ea += __shfl_xor_sync(0xFFFFFFFFu, ea, 4);
        ep += __shfl_xor_sync(0xFFFFFFFFu, ep, 4);

        if (m == 0) {
            float mk   = __ldg(mask + item);
            float loss = -(mx + __logf(ea) - __logf(ep));
            atomicAdd(&s_num[t], loss * mk);
            atomicAdd(&s_den[t], mk);
        }
    }
    __syncthreads();

    // ---- Spread global accumulation (GRID/NSLOT = 60 blocks per address) ----
    const int slot = blockIdx.x & (NSLOT - 1);
    if (tid < T_) {
        atomicAdd(&g_accn[tid * NSLOT + slot], s_num[tid]);
        atomicAdd(&g_accd[tid * NSLOT + slot], s_den[tid]);
    }

    // ---- Last-block finalize (ticket), then self-reset for replay ----
    __threadfence();
    if (tid == 0) s_last = atomicAdd(&g_ticket, 1u);
    __syncthreads();

    if (s_last == (unsigned int)(gridDim.x - 1)) {
        __threadfence();
        double v = 0.0;
        if (tid < T_) {
            const float4* pn = reinterpret_cast<const float4*>(g_accn + tid * NSLOT);
            const float4* pd = reinterpret_cast<const float4*>(g_accd + tid * NSLOT);
            double num = 0.0, den = 0.0;
            #pragma unroll 8
            for (int j = 0; j < NSLOT / 4; j++) {
                float4 a = pn[j];
                float4 b = pd[j];
                num += (double)a.x + (double)a.y + (double)a.z + (double)a.w;
                den += (double)b.x + (double)b.y + (double)b.z + (double)b.w;
            }
            v = num / den;
        }
        #pragma unroll
        for (int off = 16; off > 0; off >>= 1)
            v += __shfl_down_sync(0xFFFFFFFFu, v, off);
        __shared__ double partial[2];
        if (tid == 0)  partial[0] = v;
        if (tid == 32) partial[1] = v;
        __syncthreads();
        if (tid == 0) out[0] = (float)(partial[0] + partial[1]);
        for (int i = tid; i < T_ * NSLOT; i += BLK) {
            g_accn[i] = 0.0f;
            g_accd[i] = 0.0f;
        }
        if (tid == 0) g_ticket = 0u;
    }
}

extern "C" void kernel_launch(void* const* d_in, const int* in_sizes, int n_in,
                              void* d_out, int out_size) {
    const float* mu    = (const float*)d_in[0];
    const float* sigma = (const float*)d_in[1];
    const float* pi    = (const float*)d_in[2];
    const float* x     = (const float*)d_in[3];
    const float* mask  = (const float*)d_in[4];
    float* out = (float*)d_out;

    nll_fused_kernel<<<GRID, BLK>>>(mu, sigma, pi, x, mask, out);
}